// round 11
// baseline (speedup 1.0000x reference)
#include <cuda_runtime.h>

#define NN      51
#define HIDN    64
#define HEADS   4
#define DTOT    256     // HEADS*HIDN
#define OUTG    128
#define LH      32
#define NC      8
#define BBATCH  256
#define FFEAT   50
#define GG      (BBATCH*FFEAT)   // 12800
#define SLOPEF  0.01f
#define WPB     8                // warps (graphs) per gat block

// ---------------- scratch (no allocs allowed) ----------------
__device__ float  d_u[16];               // per-head (usrc0,usrc1,udst0,udst1)
__device__ float4 d_vcomb[DTOT];         // (vs, vd, wbar, 0)
__device__ float4 d_WihT0p[NN * 32];     // packed: [n][lane] = W^T[n][lane,+32,+64,+96]
__device__ float4 d_b0p[32];             // packed b0
__device__ float  d_b1[OUTG];
__device__ float  d_xp0[GG * OUTG];      // LSTM layer0 gate pre-activations
__device__ float  d_hseq[GG * LH];       // layer1 hidden outputs

// ---------------- helpers ----------------
__device__ __forceinline__ float fsig(float x) {
    return 1.0f / (1.0f + __expf(-x));
}
__device__ __forceinline__ float ftanhf(float x) {
    float e = __expf(-2.0f * fabsf(x));
    float r = __fdividef(1.0f - e, 1.0f + e);
    return copysignf(r, x);
}

// ---------------- kernel A: precompute (validated R9, 6.2us) ----------------
__global__ void prep_kernel(const float* __restrict__ W1, const float* __restrict__ a1,
                            const float* __restrict__ W2, const float* __restrict__ a2,
                            const float* __restrict__ Wih0,
                            const float* __restrict__ bih0, const float* __restrict__ bhh0,
                            const float* __restrict__ bih1, const float* __restrict__ bhh1) {
    int t = threadIdx.x;   // 128 threads
    int bid = blockIdx.x;
    if (bid < DTOT) {
        // one block per feature dim d: reduce over o (128 outputs)
        __shared__ float rs[3][128];
        int d = bid;
        float w = W2[t * DTOT + d];      // o = t
        rs[0][t] = w * a2[t];
        rs[1][t] = w * a2[OUTG + t];
        rs[2][t] = w;
        __syncthreads();
        if (t < 64) {
            rs[0][t] += rs[0][t + 64];
            rs[1][t] += rs[1][t + 64];
            rs[2][t] += rs[2][t + 64];
        }
        __syncthreads();
        if (t < 32) {
            float v0 = rs[0][t] + rs[0][t + 32];
            float v1 = rs[1][t] + rs[1][t + 32];
            float v2 = rs[2][t] + rs[2][t + 32];
#pragma unroll
            for (int off = 16; off; off >>= 1) {
                v0 += __shfl_down_sync(0xffffffffu, v0, off);
                v1 += __shfl_down_sync(0xffffffffu, v1, off);
                v2 += __shfl_down_sync(0xffffffffu, v2, off);
            }
            if (t == 0) d_vcomb[d] = make_float4(v0, v1, v2 * (1.0f / OUTG), 0.f);
        }
    } else if (bid < DTOT + 13) {
        // packed transpose of Wih0: 51*32 float4 items
        int idx = (bid - DTOT) * 128 + t;
        if (idx < NN * 32) {
            int n = idx >> 5, l = idx & 31;
            d_WihT0p[idx] = make_float4(Wih0[l * NN + n], Wih0[(l + 32) * NN + n],
                                        Wih0[(l + 64) * NN + n], Wih0[(l + 96) * NN + n]);
        }
    } else {
        // misc: u, b0p, b1
        if (t < 16) {
            int h = t >> 2, which = t & 3;
            int c = which & 1, side = which >> 1;
            float s = 0.f;
            for (int o = 0; o < HIDN; o++)
                s += W1[(h * HIDN + o) * 2 + c] * a1[h * 2 * HIDN + side * HIDN + o];
            d_u[t] = s;
        }
        if (t < 32)
            d_b0p[t] = make_float4(bih0[t] + bhh0[t], bih0[t + 32] + bhh0[t + 32],
                                   bih0[t + 64] + bhh0[t + 64], bih0[t + 96] + bhh0[t + 96]);
        if (t < OUTG) d_b1[t] = bih1[t] + bhh1[t];
    }
}

// ---------------- kernel B: fused GAT (warp-per-graph) + xp0 projection ----------------
__global__ void __launch_bounds__(256) gat_kernel(const float* __restrict__ feat,
                                                  const float* __restrict__ W1g) {
    __shared__ float2 W1s[DTOT];
    __shared__ float4 vcomb[DTOT];
    __shared__ float  us[16];
    __shared__ float2 xv[WPB][NN];
    __shared__ float2 PR[WPB][HEADS][NN];
    __shared__ float2 ssm[WPB][HEADS][NN];
    __shared__ float4 P2z[WPB][NN];
    __shared__ float2 Q2[WPB][NN];
    __shared__ float  extsm[WPB][52];

    int t = threadIdx.x, w = t >> 5, lane = t & 31;
    int g = blockIdx.x * WPB + w;

    if (t < DTOT) { W1s[t] = ((const float2*)W1g)[t]; vcomb[t] = d_vcomb[t]; }
    if (t < 16) us[t] = d_u[t];
    {
        const float2* x2 = (const float2*)feat + (size_t)g * NN;
        for (int i = lane; i < NN; i += 32) xv[w][i] = x2[i];
    }
    __syncthreads();

    // stage 1: GAT1 logits + exps
    float2 q[HEADS][2];
#pragma unroll
    for (int h = 0; h < HEADS; h++) {
        float u0 = us[h * 4 + 0], u1 = us[h * 4 + 1], u2 = us[h * 4 + 2], u3 = us[h * 4 + 3];
#pragma unroll
        for (int jb = 0; jb < 2; jb++) {
            int j = jb * 32 + lane;
            float2 xn = (j < NN) ? xv[w][j] : make_float2(0.f, 0.f);
            float es = xn.x * u0 + xn.y * u1;
            float ed = xn.x * u2 + xn.y * u3;
            if (j < NN) PR[w][h][j] = make_float2(__expf(es), __expf(SLOPEF * es));
            q[h][jb] = make_float2(__expf(ed), __expf(SLOPEF * ed));
        }
    }
    __syncwarp();

    // stage 2: attention-weighted feature sums
#pragma unroll
    for (int h = 0; h < HEADS; h++) {
        float2 q0 = q[h][0], q1 = q[h][1];
        float den0 = 0.f, s00 = 0.f, s01 = 0.f;
        float den1 = 0.f, s10 = 0.f, s11 = 0.f;
#pragma unroll 3
        for (int i = 0; i < NN; i++) {
            float2 pr = PR[w][h][i];
            float2 xi = xv[w][i];
            float w0 = fmaxf(pr.x * q0.x, pr.y * q0.y);
            float w1 = fmaxf(pr.x * q1.x, pr.y * q1.y);
            den0 += w0; s00 += w0 * xi.x; s01 += w0 * xi.y;
            den1 += w1; s10 += w1 * xi.x; s11 += w1 * xi.y;
        }
        {
            int j0 = lane;
            float2 pr = PR[w][h][j0]; float2 xj = xv[w][j0];
            float w0 = fmaxf(pr.x * q0.x, pr.y * q0.y);
            den0 -= w0; s00 -= w0 * xj.x; s01 -= w0 * xj.y;
            float inv = __fdividef(1.0f, den0);
            ssm[w][h][j0] = make_float2(s00 * inv, s01 * inv);
        }
        int j1 = 32 + lane;
        if (j1 < NN) {
            float2 pr = PR[w][h][j1]; float2 xj = xv[w][j1];
            float w1 = fmaxf(pr.x * q1.x, pr.y * q1.y);
            den1 -= w1; s10 -= w1 * xj.x; s11 -= w1 * xj.y;
            float inv = __fdividef(1.0f, den1);
            ssm[w][h][j1] = make_float2(s10 * inv, s11 * inv);
        }
    }
    __syncwarp();

    // stage 3: elu(h1) projections -> es2, ed2, zbar
    {
        int grp = lane >> 3, gl = lane & 7;
#pragma unroll 1
        for (int p = 0; p < 13; p++) {
            int j = p * 4 + grp;
            bool valid = (j < NN);
            int jc = valid ? j : 0;
            float2 sh[HEADS];
#pragma unroll
            for (int h = 0; h < HEADS; h++) sh[h] = ssm[w][h][jc];
            float a_es = 0.f, a_ed = 0.f, a_zb = 0.f;
#pragma unroll
            for (int h = 0; h < HEADS; h++) {
                float sx = sh[h].x, sy = sh[h].y;
#pragma unroll
                for (int kk = 0; kk < 8; kk++) {
                    int d = h * 64 + kk * 8 + gl;
                    float2 wv = W1s[d];
                    float h1 = sx * wv.x + sy * wv.y;
                    float he = (h1 > 0.f) ? h1 : (__expf(h1) - 1.0f);
                    float4 vc = vcomb[d];
                    a_es += he * vc.x; a_ed += he * vc.y; a_zb += he * vc.z;
                }
            }
#pragma unroll
            for (int off = 4; off; off >>= 1) {
                a_es += __shfl_down_sync(0xffffffffu, a_es, off);
                a_ed += __shfl_down_sync(0xffffffffu, a_ed, off);
                a_zb += __shfl_down_sync(0xffffffffu, a_zb, off);
            }
            if (gl == 0 && valid) {
                P2z[w][j] = make_float4(__expf(a_es), __expf(SLOPEF * a_es), a_zb, 0.f);
                Q2[w][j] = make_float2(__expf(a_ed), __expf(SLOPEF * a_ed));
            }
        }
    }
    __syncwarp();

    // stage 5: GAT2 attention -> extracted (into smem)
#pragma unroll
    for (int jb = 0; jb < 2; jb++) {
        int j = jb * 32 + lane;
        if (j < NN) {
            float2 qq = Q2[w][j];
            float den = 0.f, acc = 0.f;
#pragma unroll 3
            for (int i = 0; i < NN; i++) {
                float4 p = P2z[w][i];
                float w_ = fmaxf(p.x * qq.x, p.y * qq.y);
                den += w_; acc += w_ * p.z;
            }
            float4 p = P2z[w][j];
            float w_ = fmaxf(p.x * qq.x, p.y * qq.y);
            den -= w_; acc -= w_ * p.z;
            extsm[w][j] = acc * __fdividef(1.0f, den);
        }
    }
    __syncwarp();

    // stage 6: xp0 = ext @ WihT0 + b0 (per-lane 4 cols)
    {
        float4 acc = d_b0p[lane];
#pragma unroll 4
        for (int n = 0; n < NN; n++) {
            float e = extsm[w][n];
            float4 wv = __ldg(&d_WihT0p[n * 32 + lane]);
            acc.x += e * wv.x; acc.y += e * wv.y;
            acc.z += e * wv.z; acc.w += e * wv.w;
        }
        float* xg = d_xp0 + (size_t)g * OUTG;
        xg[lane] = acc.x; xg[lane + 32] = acc.y;
        xg[lane + 64] = acc.z; xg[lane + 96] = acc.w;
    }
}

// ---------------- kernel C: pipelined 2-layer LSTM (standalone, no handshake) ----------------
__global__ void __launch_bounds__(256) lstm_kernel(const float* __restrict__ Whh0,
                                                   const float* __restrict__ Wih1,
                                                   const float* __restrict__ Whh1) {
    __shared__ __align__(16) float h0[LH];
    __shared__ __align__(16) float h1s[LH];
    __shared__ __align__(16) float g0[OUTG];
    __shared__ __align__(16) float g1[OUTG];
    __shared__ __align__(16) float xps[2][OUTG];

    int f = blockIdx.x;    // 50 blocks
    int t = threadIdx.x;   // 256 threads

    float wa[32], wbv[32];
    if (t < OUTG) {
#pragma unroll
        for (int k = 0; k < 32; k++) wa[k] = Whh0[t * 32 + k];
    } else {
        int r = t - OUTG;
#pragma unroll
        for (int k = 0; k < 32; k++) { wa[k] = Wih1[r * 32 + k]; wbv[k] = Whh1[r * 32 + k]; }
    }
    float b1v = (t >= OUTG) ? d_b1[t - OUTG] : 0.f;
    float c_ = 0.f;
    if (t < LH) { h0[t] = 0.f; h1s[t] = 0.f; }

    // prologue: xp for steps 0,1 into smem; step 2 into pipeline register
    if (t < OUTG) {
        xps[0][t] = d_xp0[(size_t)f * OUTG + t];
        xps[1][t] = d_xp0[((size_t)FFEAT + f) * OUTG + t];
    }
    float ldreg = 0.f;
    if (t >= 64 && t < 192) ldreg = d_xp0[((size_t)2 * FFEAT + f) * OUTG + (t - 64)];
    __syncthreads();

    for (int k = 0; k <= BBATCH; k++) {
        // ---- phase A: gate dots (layer0 @ k, layer1 @ k-1) ----
        if (t < OUTG) {
            if (k < BBATCH) {
                const float4* h4 = (const float4*)h0;
                float xpv = xps[k & 1][t];
                float a0 = 0.f, a1_ = 0.f, a2_ = 0.f, a3 = 0.f;
#pragma unroll
                for (int jj = 0; jj < 8; jj++) {
                    float4 hv = h4[jj];
                    a0 += wa[4 * jj] * hv.x;
                    a1_ += wa[4 * jj + 1] * hv.y;
                    a2_ += wa[4 * jj + 2] * hv.z;
                    a3 += wa[4 * jj + 3] * hv.w;
                }
                g0[t] = xpv + ((a0 + a1_) + (a2_ + a3));
            }
        } else if (k >= 1) {
            int r = t - OUTG;
            const float4* h4 = (const float4*)h0;
            const float4* h14 = (const float4*)h1s;
            float a0 = 0.f, a1_ = 0.f, a2_ = 0.f, a3 = 0.f;
#pragma unroll
            for (int jj = 0; jj < 8; jj++) {
                float4 hv = h4[jj]; float4 hw = h14[jj];
                a0 += wa[4 * jj] * hv.x + wbv[4 * jj] * hw.x;
                a1_ += wa[4 * jj + 1] * hv.y + wbv[4 * jj + 1] * hw.y;
                a2_ += wa[4 * jj + 2] * hv.z + wbv[4 * jj + 2] * hw.z;
                a3 += wa[4 * jj + 3] * hv.w + wbv[4 * jj + 3] * hw.w;
            }
            g1[r] = b1v + ((a0 + a1_) + (a2_ + a3));
        }
        __syncthreads();
        // ---- phase B: state updates + xp prefetch pipeline ----
        if (t < 32) {
            if (k < BBATCH) {
                float gi = g0[t], gf = g0[32 + t], gg = g0[64 + t], go = g0[96 + t];
                c_ = fsig(gf) * c_ + fsig(gi) * ftanhf(gg);
                h0[t] = fsig(go) * ftanhf(c_);
            }
        } else if (t < 64) {
            if (k >= 1) {
                int r = t - 32;
                float gi = g1[r], gf = g1[32 + r], gg = g1[64 + r], go = g1[96 + r];
                c_ = fsig(gf) * c_ + fsig(gi) * ftanhf(gg);
                float hn = fsig(go) * ftanhf(c_);
                h1s[r] = hn;
                d_hseq[(((size_t)(k - 1)) * FFEAT + f) * LH + r] = hn;
            }
        } else if (t < 192) {
            int col = t - 64;
            if (k + 2 < BBATCH) xps[k & 1][col] = ldreg;   // xp for step k+2
            if (k + 3 < BBATCH)
                ldreg = __ldcg(&d_xp0[((size_t)(k + 3) * FFEAT + f) * OUTG + col]);
        }
        __syncthreads();
    }
}

// ---------------- kernel D: final FC ----------------
__global__ void __launch_bounds__(256) fc_kernel(const float* __restrict__ Wfc,
                                                 const float* __restrict__ bfc,
                                                 float* __restrict__ out) {
    int b = blockIdx.x;          // 256 blocks
    int t = threadIdx.x;
    int k = t >> 5, lane = t & 31;   // 8 warps = 8 classes
    const float* y = d_hseq + (size_t)b * (FFEAT * LH);
    const float* w = Wfc + (size_t)k * (FFEAT * LH);
    float acc = 0.f;
    for (int i = lane; i < FFEAT * LH; i += 32)
        acc += y[i] * w[i];
#pragma unroll
    for (int off = 16; off; off >>= 1)
        acc += __shfl_down_sync(0xffffffffu, acc, off);
    if (lane == 0) out[b * NC + k] = acc + bfc[k];
}

// ---------------- launch ----------------
extern "C" void kernel_launch(void* const* d_in, const int* in_sizes, int n_in,
                              void* d_out, int out_size) {
    const float* feat = (const float*)d_in[0];
    const float* W1   = (const float*)d_in[1];
    const float* a1   = (const float*)d_in[2];
    const float* W2   = (const float*)d_in[3];
    const float* a2   = (const float*)d_in[4];
    const float* Wih0 = (const float*)d_in[5];
    const float* Whh0 = (const float*)d_in[6];
    const float* bih0 = (const float*)d_in[7];
    const float* bhh0 = (const float*)d_in[8];
    const float* Wih1 = (const float*)d_in[9];
    const float* Whh1 = (const float*)d_in[10];
    const float* bih1 = (const float*)d_in[11];
    const float* bhh1 = (const float*)d_in[12];
    const float* Wfc  = (const float*)d_in[13];
    const float* bfc  = (const float*)d_in[14];
    float* out = (float*)d_out;

    prep_kernel<<<DTOT + 13 + 1, 128>>>(W1, a1, W2, a2, Wih0, bih0, bhh0, bih1, bhh1);
    gat_kernel<<<GG / WPB, 256>>>(feat, W1);
    lstm_kernel<<<FFEAT, 256>>>(Whh0, Wih1, Whh1);
    fc_kernel<<<BBATCH, 256>>>(Wfc, bfc, out);
}